// round 13
// baseline (speedup 1.0000x reference)
#include <cuda_runtime.h>
#include <cuda_bf16.h>
#include <cuda_fp16.h>
#include <cstdint>
#include <math.h>

#define Bb 2
#define Ss 2048
#define Dd 1024
#define Hh 16
#define DKk 64
#define TQ 16
#define NT 512
#define TH 0.1f

// ---------------- scratch (__device__ globals; no allocs allowed) ----------
__device__ float g_q [Bb*Ss*Dd];
__device__ float g_k [Bb*Ss*Dd];
__device__ float g_v [Bb*Ss*Dd];
__device__ float g_m [Bb*Ss*Dd];
__device__ __nv_bfloat16 g_qhi[Bb*Ss*Dd], g_qlo[Bb*Ss*Dd];
__device__ __nv_bfloat16 g_khi[Bb*Ss*Dd], g_klo[Bb*Ss*Dd];
__device__ __nv_bfloat16 g_xhi[Bb*Ss*Dd], g_xlo[Bb*Ss*Dd];
__device__ __nv_bfloat16 g_mhi[Bb*Ss*Dd], g_mlo[Bb*Ss*Dd];
__device__ __nv_bfloat16 g_whi[4*Dd*Dd],  g_wlo[4*Dd*Dd];
__device__ __half g_e[(size_t)Bb*Hh*Ss*Ss];          // exp'd scores, 268 MB
__device__ float  g_rsp[(size_t)Bb*Hh*Ss*16];        // partial row sums, 4 MB

extern __shared__ char smraw[];

// ---------------- mma.sync / cp.async helpers (base ISA) -------------------
__device__ __forceinline__ uint32_t smem_u32(const void* p) {
    uint32_t a;
    asm("{ .reg .u64 t; cvta.to.shared.u64 t, %1; cvt.u32.u64 %0, t; }" : "=r"(a) : "l"(p));
    return a;
}
__device__ __forceinline__ void ldsm_x4(uint32_t& r0, uint32_t& r1, uint32_t& r2,
                                        uint32_t& r3, uint32_t addr) {
    asm volatile("ldmatrix.sync.aligned.m8n8.x4.shared.b16 {%0,%1,%2,%3}, [%4];"
                 : "=r"(r0), "=r"(r1), "=r"(r2), "=r"(r3) : "r"(addr));
}
__device__ __forceinline__ void ldsm_x2(uint32_t& r0, uint32_t& r1, uint32_t addr) {
    asm volatile("ldmatrix.sync.aligned.m8n8.x2.shared.b16 {%0,%1}, [%2];"
                 : "=r"(r0), "=r"(r1) : "r"(addr));
}
__device__ __forceinline__ void mma_bf16(float* d, const uint32_t* a, const uint32_t* b) {
    asm volatile(
        "mma.sync.aligned.m16n8k16.row.col.f32.bf16.bf16.f32 "
        "{%0,%1,%2,%3}, {%4,%5,%6,%7}, {%8,%9}, {%0,%1,%2,%3};"
        : "+f"(d[0]), "+f"(d[1]), "+f"(d[2]), "+f"(d[3])
        : "r"(a[0]), "r"(a[1]), "r"(a[2]), "r"(a[3]), "r"(b[0]), "r"(b[1]));
}
__device__ __forceinline__ void cp16(uint32_t saddr, const void* gaddr) {
    asm volatile("cp.async.cg.shared.global [%0], [%1], 16;"
                 :: "r"(saddr), "l"(gaddr) : "memory");
}
#define CP_COMMIT() asm volatile("cp.async.commit_group;" ::: "memory")
#define CP_WAIT(n)  asm volatile("cp.async.wait_group %0;" :: "n"(n) : "memory")

// ---------------------------------------------------------------------------
// splits
// ---------------------------------------------------------------------------
__device__ __forceinline__ void split_one(float4 v, __nv_bfloat162* hi,
                                          __nv_bfloat162* lo, int i) {
    __nv_bfloat16 hx = __float2bfloat16(v.x);
    __nv_bfloat16 hy = __float2bfloat16(v.y);
    __nv_bfloat16 hz = __float2bfloat16(v.z);
    __nv_bfloat16 hw = __float2bfloat16(v.w);
    hi[2*i]   = __halves2bfloat162(hx, hy);
    hi[2*i+1] = __halves2bfloat162(hz, hw);
    lo[2*i]   = __halves2bfloat162(__float2bfloat16(v.x - __bfloat162float(hx)),
                                   __float2bfloat16(v.y - __bfloat162float(hy)));
    lo[2*i+1] = __halves2bfloat162(__float2bfloat16(v.z - __bfloat162float(hz)),
                                   __float2bfloat16(v.w - __bfloat162float(hw)));
}

__global__ __launch_bounds__(256) void split4(
    const float4* __restrict__ x, __nv_bfloat162* __restrict__ hi,
    __nv_bfloat162* __restrict__ lo, int n4)
{
    int i = blockIdx.x * 256 + threadIdx.x;
    if (i >= n4) return;
    split_one(x[i], hi, lo, i);
}

__global__ __launch_bounds__(256) void split4w(
    const float4* __restrict__ w0, const float4* __restrict__ w1,
    const float4* __restrict__ w2, const float4* __restrict__ w3,
    __nv_bfloat162* __restrict__ hi, __nv_bfloat162* __restrict__ lo, int n4)
{
    int z = blockIdx.z;
    const float4* src = (z == 0) ? w0 : (z == 1) ? w1 : (z == 2) ? w2 : w3;
    int i = blockIdx.x * 256 + threadIdx.x;
    if (i >= n4) return;
    split_one(src[i], hi + (size_t)z * n4 * 2, lo + (size_t)z * n4 * 2, i);
}

// ---------------------------------------------------------------------------
// HMMA GEMM body (cp.async double buffer) — projections.
// ---------------------------------------------------------------------------
#define SROW 40
#define STAGE_B (4 * 128 * SROW * 2)
#define A_HI_B  0
#define A_LO_B  (128 * SROW * 2)
#define B_HI_B  (2 * 128 * SROW * 2)
#define B_LO_B  (3 * 128 * SROW * 2)
#define GEMM_SMEM (2 * STAGE_B)

__device__ __forceinline__ void gemm_body(
    const __nv_bfloat16* __restrict__ Ahi, const __nv_bfloat16* __restrict__ Alo,
    const __nv_bfloat16* __restrict__ Whi, const __nv_bfloat16* __restrict__ Wlo,
    const float* __restrict__ bias, float* __restrict__ C,
    __nv_bfloat16* __restrict__ Chi, __nv_bfloat16* __restrict__ Clo,
    int Kdim, int Ndim)
{
    const uint32_t sbase = smem_u32(smraw);
    const int tid = threadIdx.x, lane = tid & 31, wid = tid >> 5;
    const int wm = (wid >> 2) * 64;
    const int wn = (wid & 3) * 32;
    const int n0 = blockIdx.x * 128, m0 = blockIdx.y * 128;

    uint32_t aoff[4], boff[4];
    #pragma unroll
    for (int mt = 0; mt < 4; ++mt)
        aoff[mt] = ((wm + mt * 16 + (lane & 15)) * SROW + (lane >> 4) * 8) * 2;
    #pragma unroll
    for (int nt = 0; nt < 4; ++nt)
        boff[nt] = ((wn + nt * 8 + (lane & 7)) * SROW + ((lane >> 3) & 1) * 8) * 2;

    const int r0 = tid >> 2,          c0 = (tid & 3) * 8;
    const int r1 = (tid + 256) >> 2,  c1 = ((tid + 256) & 3) * 8;
    const uint32_t s_off0 = (uint32_t)(r0 * SROW + c0) * 2;
    const uint32_t s_off1 = (uint32_t)(r1 * SROW + c1) * 2;

    const __nv_bfloat16* ga0h = Ahi + (size_t)(m0 + r0) * Kdim + c0;
    const __nv_bfloat16* ga1h = Ahi + (size_t)(m0 + r1) * Kdim + c1;
    const __nv_bfloat16* ga0l = Alo + (size_t)(m0 + r0) * Kdim + c0;
    const __nv_bfloat16* ga1l = Alo + (size_t)(m0 + r1) * Kdim + c1;
    const __nv_bfloat16* gb0h = Whi + (size_t)(n0 + r0) * Kdim + c0;
    const __nv_bfloat16* gb1h = Whi + (size_t)(n0 + r1) * Kdim + c1;
    const __nv_bfloat16* gb0l = Wlo + (size_t)(n0 + r0) * Kdim + c0;
    const __nv_bfloat16* gb1l = Wlo + (size_t)(n0 + r1) * Kdim + c1;

    float d[4][4][4];
    #pragma unroll
    for (int mt = 0; mt < 4; ++mt)
        #pragma unroll
        for (int nt = 0; nt < 4; ++nt)
            #pragma unroll
            for (int i = 0; i < 4; ++i) d[mt][nt][i] = 0.f;

    const int nkt = Kdim >> 5;

    auto load_stage = [&](int stg, int kt) {
        const int kb = kt << 5;
        const uint32_t s = sbase + (uint32_t)stg * STAGE_B;
        cp16(s + A_HI_B + s_off0, ga0h + kb);
        cp16(s + A_HI_B + s_off1, ga1h + kb);
        cp16(s + A_LO_B + s_off0, ga0l + kb);
        cp16(s + A_LO_B + s_off1, ga1l + kb);
        cp16(s + B_HI_B + s_off0, gb0h + kb);
        cp16(s + B_HI_B + s_off1, gb1h + kb);
        cp16(s + B_LO_B + s_off0, gb0l + kb);
        cp16(s + B_LO_B + s_off1, gb1l + kb);
        CP_COMMIT();
    };

    load_stage(0, 0);

    for (int kt = 0; kt < nkt; ++kt) {
        if (kt + 1 < nkt) { load_stage((kt + 1) & 1, kt + 1); CP_WAIT(1); }
        else              { CP_WAIT(0); }
        __syncthreads();

        const uint32_t s = sbase + (uint32_t)(kt & 1) * STAGE_B;
        #pragma unroll
        for (int ks = 0; ks < 2; ++ks) {
            const uint32_t kadd = ks * 32;
            uint32_t ah[4][4], al[4][4], bh[4][2], bl[4][2];
            #pragma unroll
            for (int mt = 0; mt < 4; ++mt) {
                ldsm_x4(ah[mt][0], ah[mt][1], ah[mt][2], ah[mt][3],
                        s + A_HI_B + aoff[mt] + kadd);
                ldsm_x4(al[mt][0], al[mt][1], al[mt][2], al[mt][3],
                        s + A_LO_B + aoff[mt] + kadd);
            }
            #pragma unroll
            for (int nt = 0; nt < 4; ++nt) {
                ldsm_x2(bh[nt][0], bh[nt][1], s + B_HI_B + boff[nt] + kadd);
                ldsm_x2(bl[nt][0], bl[nt][1], s + B_LO_B + boff[nt] + kadd);
            }
            #pragma unroll
            for (int mt = 0; mt < 4; ++mt)
                #pragma unroll
                for (int nt = 0; nt < 4; ++nt) {
                    mma_bf16(d[mt][nt], ah[mt], bh[nt]);
                    mma_bf16(d[mt][nt], ah[mt], bl[nt]);
                    mma_bf16(d[mt][nt], al[mt], bh[nt]);
                }
        }
        __syncthreads();
    }

    const int g = lane >> 2, c2 = (lane & 3) * 2;
    #pragma unroll
    for (int mt = 0; mt < 4; ++mt) {
        #pragma unroll
        for (int nt = 0; nt < 4; ++nt) {
            int m = m0 + wm + mt * 16 + g;
            int n = n0 + wn + nt * 8 + c2;
            float bx = bias[n], by = bias[n + 1];
            float2 o0 = make_float2(d[mt][nt][0] + bx, d[mt][nt][1] + by);
            float2 o1 = make_float2(d[mt][nt][2] + bx, d[mt][nt][3] + by);
            *(float2*)(C + (size_t)m * Ndim + n) = o0;
            *(float2*)(C + (size_t)(m + 8) * Ndim + n) = o1;
            if (Chi) {
                __nv_bfloat16 h0x = __float2bfloat16(o0.x), h0y = __float2bfloat16(o0.y);
                __nv_bfloat16 h1x = __float2bfloat16(o1.x), h1y = __float2bfloat16(o1.y);
                size_t i0 = (size_t)m * Ndim + n, i1 = (size_t)(m + 8) * Ndim + n;
                Chi[i0] = h0x; Chi[i0 + 1] = h0y;
                Chi[i1] = h1x; Chi[i1 + 1] = h1y;
                Clo[i0]     = __float2bfloat16(o0.x - __bfloat162float(h0x));
                Clo[i0 + 1] = __float2bfloat16(o0.y - __bfloat162float(h0y));
                Clo[i1]     = __float2bfloat16(o1.x - __bfloat162float(h1x));
                Clo[i1 + 1] = __float2bfloat16(o1.y - __bfloat162float(h1y));
            }
        }
    }
}

__global__ __launch_bounds__(256, 2)
void gemm_qkv(const __nv_bfloat16* __restrict__ Ahi, const __nv_bfloat16* __restrict__ Alo,
              const __nv_bfloat16* __restrict__ Whi, const __nv_bfloat16* __restrict__ Wlo,
              const float* bq, const float* bk, const float* bv,
              float* Cq, float* Ck, float* Cv,
              __nv_bfloat16* qhi, __nv_bfloat16* qlo,
              __nv_bfloat16* khi, __nv_bfloat16* klo,
              int Kdim, int Ndim)
{
    const int z = blockIdx.z;
    const size_t NW = (size_t)Kdim * Ndim;
    const float* bias = (z == 0) ? bq : (z == 1) ? bk : bv;
    float* C = (z == 0) ? Cq : (z == 1) ? Ck : Cv;
    __nv_bfloat16* Chi = (z == 0) ? qhi : (z == 1) ? khi : (__nv_bfloat16*)nullptr;
    __nv_bfloat16* Clo = (z == 0) ? qlo : (z == 1) ? klo : (__nv_bfloat16*)nullptr;
    gemm_body(Ahi, Alo, Whi + z * NW, Wlo + z * NW, bias, C, Chi, Clo, Kdim, Ndim);
}

__global__ __launch_bounds__(256, 2)
void gemm_o(const __nv_bfloat16* __restrict__ Ahi, const __nv_bfloat16* __restrict__ Alo,
            const __nv_bfloat16* __restrict__ Whi, const __nv_bfloat16* __restrict__ Wlo,
            const float* __restrict__ bias, float* __restrict__ C, int Kdim, int Ndim)
{
    gemm_body(Ahi, Alo, Whi, Wlo, bias, C, nullptr, nullptr, Kdim, Ndim);
}

// ---------------------------------------------------------------------------
// fast exp (FMA pipe only)
// ---------------------------------------------------------------------------
__device__ __forceinline__ float fexp(float x) {
    x = fmaxf(x, -87.0f);
    float p = x * 1.44269504088896340f;
    int   ni = __float2int_rn(p);
    float f  = p - (float)ni;
    float t  = f * 0.69314718055994531f;
    float r  = 1.9841269841269841e-4f;
    r = fmaf(r, t, 1.3888888888888889e-3f);
    r = fmaf(r, t, 8.3333333333333333e-3f);
    r = fmaf(r, t, 4.1666666666666664e-2f);
    r = fmaf(r, t, 1.6666666666666666e-1f);
    r = fmaf(r, t, 0.5f);
    r = fmaf(r, t, 1.0f);
    r = fmaf(r, t, 1.0f);
    return r * __int_as_float((ni + 127) << 23);
}

// ---------------------------------------------------------------------------
// score_gemm: E[b,h,q,k] = exp(Q·K^T / 8) in fp16 + per-tile partial row sums.
// One 128x128 tile per block, K=64 single-shot, split-bf16 3-pass HMMA.
// grid (16 ktile, 16 qtile, 32 bh), 256 threads, 2 CTAs/SM.
// ---------------------------------------------------------------------------
#define KSTR 72
#define SA_HI 0
#define SA_LO 18432
#define SB_HI 36864
#define SB_LO 55296
#define RS_O  73728
#define SG_SMEM (73728 + 512)

__global__ __launch_bounds__(256, 2)
void score_gemm(const __nv_bfloat16* __restrict__ QHI, const __nv_bfloat16* __restrict__ QLO,
                const __nv_bfloat16* __restrict__ KHI, const __nv_bfloat16* __restrict__ KLO,
                __half* __restrict__ E, float* __restrict__ rsp)
{
    char* smb = smraw;
    const uint32_t sbase = smem_u32(smb);
    const int tid = threadIdx.x, lane = tid & 31, wid = tid >> 5;
    const int k0 = blockIdx.x * 128, q0 = blockIdx.y * 128;
    const int z = blockIdx.z;                  // b*16 + h
    const int b = z >> 4, h = z & 15;

    const __nv_bfloat16* Qh = QHI + ((size_t)b * Ss + q0) * Dd + h * DKk;
    const __nv_bfloat16* Ql = QLO + ((size_t)b * Ss + q0) * Dd + h * DKk;
    const __nv_bfloat16* Kh = KHI + ((size_t)b * Ss + k0) * Dd + h * DKk;
    const __nv_bfloat16* Kl = KLO + ((size_t)b * Ss + k0) * Dd + h * DKk;

    // load 128x64 tiles (hi+lo for Q and K)
    #pragma unroll
    for (int s = 0; s < 4; ++s) {
        int slot = tid + s * 256;
        int row = slot >> 3, c = (slot & 7) * 8;
        size_t go = (size_t)row * Dd + c;
        uint32_t so = (uint32_t)(row * KSTR + c) * 2;
        cp16(sbase + SA_HI + so, Qh + go);
        cp16(sbase + SA_LO + so, Ql + go);
        cp16(sbase + SB_HI + so, Kh + go);
        cp16(sbase + SB_LO + so, Kl + go);
    }
    CP_COMMIT();
    CP_WAIT(0);
    __syncthreads();

    const int wm = (wid >> 2) * 64;
    const int wn = (wid & 3) * 32;
    uint32_t aoff[4], boff[4];
    #pragma unroll
    for (int mt = 0; mt < 4; ++mt)
        aoff[mt] = ((wm + mt * 16 + (lane & 15)) * KSTR + (lane >> 4) * 8) * 2;
    #pragma unroll
    for (int nt = 0; nt < 4; ++nt)
        boff[nt] = ((wn + nt * 8 + (lane & 7)) * KSTR + ((lane >> 3) & 1) * 8) * 2;

    float d[4][4][4];
    #pragma unroll
    for (int mt = 0; mt < 4; ++mt)
        #pragma unroll
        for (int nt = 0; nt < 4; ++nt)
            #pragma unroll
            for (int i = 0; i < 4; ++i) d[mt][nt][i] = 0.f;

    #pragma unroll
    for (int kk = 0; kk < 4; ++kk) {
        const uint32_t kadd = kk * 32;
        uint32_t ah[4][4], al[4][4], bh[4][2], bl[4][2];
        #pragma unroll
        for (int mt = 0; mt < 4; ++mt) {
            ldsm_x4(ah[mt][0], ah[mt][1], ah[mt][2], ah[mt][3],
                    sbase + SA_HI + aoff[mt] + kadd);
            ldsm_x4(al[mt][0], al[mt][1], al[mt][2], al[mt][3],
                    sbase + SA_LO + aoff[mt] + kadd);
        }
        #pragma unroll
        for (int nt = 0; nt < 4; ++nt) {
            ldsm_x2(bh[nt][0], bh[nt][1], sbase + SB_HI + boff[nt] + kadd);
            ldsm_x2(bl[nt][0], bl[nt][1], sbase + SB_LO + boff[nt] + kadd);
        }
        #pragma unroll
        for (int mt = 0; mt < 4; ++mt)
            #pragma unroll
            for (int nt = 0; nt < 4; ++nt) {
                mma_bf16(d[mt][nt], ah[mt], bh[nt]);
                mma_bf16(d[mt][nt], ah[mt], bl[nt]);
                mma_bf16(d[mt][nt], al[mt], bh[nt]);
            }
    }

    // epilogue: exp, fp16 store, per-tile row sums (deterministic)
    __syncthreads();
    float* rs = (float*)(smb + RS_O);
    if (tid < 128) rs[tid] = 0.f;
    __syncthreads();

    const int g = lane >> 2, c2 = (lane & 3) * 2;
    __half* Eb = E + ((size_t)z * Ss + q0) * Ss + k0;
    #pragma unroll
    for (int mt = 0; mt < 4; ++mt) {
        float r0 = 0.f, r1 = 0.f;
        const int rowA = wm + mt * 16 + g;
        #pragma unroll
        for (int nt = 0; nt < 4; ++nt) {
            int col = wn + nt * 8 + c2;
            float e0 = fexp(d[mt][nt][0] * 0.125f);
            float e1 = fexp(d[mt][nt][1] * 0.125f);
            float e2 = fexp(d[mt][nt][2] * 0.125f);
            float e3 = fexp(d[mt][nt][3] * 0.125f);
            *(__half2*)(Eb + (size_t)rowA * Ss + col)       = __floats2half2_rn(e0, e1);
            *(__half2*)(Eb + (size_t)(rowA + 8) * Ss + col) = __floats2half2_rn(e2, e3);
            r0 += e0 + e1;
            r1 += e2 + e3;
        }
        r0 += __shfl_xor_sync(0xffffffffu, r0, 1);
        r0 += __shfl_xor_sync(0xffffffffu, r0, 2);
        r1 += __shfl_xor_sync(0xffffffffu, r1, 1);
        r1 += __shfl_xor_sync(0xffffffffu, r1, 2);
        if ((lane & 3) == 0) {
            atomicAdd(&rs[rowA], r0);
            atomicAdd(&rs[rowA + 8], r1);
        }
    }
    __syncthreads();
    if (tid < 128)
        rsp[((size_t)z * Ss + q0 + tid) * 16 + blockIdx.x] = rs[tid];
}

// ---------------------------------------------------------------------------
// attn_stream: per (b, 16 q-rows) block; per head: inv from partials, one
// coalesced fp16 pass over E accumulating psum/pmask; rare PV path from E.
// ---------------------------------------------------------------------------
__global__ __launch_bounds__(NT)
void attn_stream(const __half* __restrict__ E, const float* __restrict__ rsp,
                 const float* __restrict__ V, float* __restrict__ merged,
                 float* __restrict__ osum, float* __restrict__ omask)
{
    __shared__ float sm_inv[16];
    const int tid  = threadIdx.x;
    const int lane = tid & 31;
    const int wid  = tid >> 5;
    const int b    = blockIdx.x >> 7;
    const int q0   = (blockIdx.x & 127) * TQ;
    const float* Vb = V + (size_t)b * Ss * Dd;

    float4   psum[TQ];
    uint32_t pm[TQ];
    #pragma unroll
    for (int q = 0; q < TQ; ++q) {
        psum[q] = make_float4(0.f, 0.f, 0.f, 0.f);
        pm[q] = 0u;
    }

    for (int h = 0; h < Hh; ++h) {
        const int z = b * Hh + h;
        const int hd = h * DKk;
        const __half* Eb = E + ((size_t)z * Ss + q0) * Ss;

        __syncthreads();                         // sm_inv reuse guard
        if (tid < 16) {
            const float* rp = rsp + ((size_t)z * Ss + q0 + tid) * 16;
            float s = 0.f;
            #pragma unroll
            for (int i = 0; i < 16; ++i) s += rp[i];
            sm_inv[tid] = 1.0f / s;
        }
        __syncthreads();
        float invf[TQ];
        #pragma unroll
        for (int q = 0; q < TQ; ++q) invf[q] = sm_inv[q];

        uint32_t anyk = 0;
        #pragma unroll
        for (int q = 0; q < TQ; ++q) {
            uint2 uu = *(const uint2*)(Eb + (size_t)q * Ss + tid * 4);
            float2 f01 = __half22float2(*reinterpret_cast<__half2*>(&uu.x));
            float2 f23 = __half22float2(*reinterpret_cast<__half2*>(&uu.y));
            float4 p4;
            p4.x = f01.x * invf[q]; p4.y = f01.y * invf[q];
            p4.z = f23.x * invf[q]; p4.w = f23.y * invf[q];
            uint32_t u = (p4.x >= TH ? 0x1u : 0u) | (p4.y >= TH ? 0x100u : 0u) |
                         (p4.z >= TH ? 0x10000u : 0u) | (p4.w >= TH ? 0x1000000u : 0u);
            pm[q] += u;
            anyk |= u;
            psum[q].x += p4.x; psum[q].y += p4.y;
            psum[q].z += p4.z; psum[q].w += p4.w;
        }
        int any = __syncthreads_or((int)anyk);

        if (any) {
            const float inv = sm_inv[wid];
            const __half* srow = Eb + (size_t)wid * Ss;
            const float* vb2 = Vb + hd + lane * 2;
            float2 ctx = make_float2(0.f, 0.f);
            for (int k = 0; k < Ss; ++k) {
                float p = __half2float(srow[k]) * inv;
                p = (p >= TH) ? p : 0.f;
                float2 vv = *(const float2*)(vb2 + (size_t)k * Dd);
                ctx.x = fmaf(p, vv.x, ctx.x);
                ctx.y = fmaf(p, vv.y, ctx.y);
            }
            *(float2*)(merged + ((size_t)b * Ss + q0 + wid) * Dd + hd + lane * 2) = ctx;
        } else {
            *(float2*)(merged + ((size_t)b * Ss + q0 + wid) * Dd + hd + lane * 2) =
                make_float2(0.f, 0.f);
        }
    }

    #pragma unroll
    for (int q = 0; q < TQ; ++q) {
        size_t row = (size_t)b * Ss + q0 + q;
        ((float4*)(osum + row * Ss))[tid] = psum[q];
        uint32_t u = pm[q];
        float4 f;
        f.x = (float)(u & 255u);
        f.y = (float)((u >> 8) & 255u);
        f.z = (float)((u >> 16) & 255u);
        f.w = (float)(u >> 24);
        ((float4*)(omask + row * Ss))[tid] = f;
    }
}

// ---------------------------------------------------------------------------
extern "C" void kernel_launch(void* const* d_in, const int* in_sizes, int n_in,
                              void* d_out, int out_size)
{
    const float* x  = (const float*)d_in[0];
    const float* Wq = (const float*)d_in[1];
    const float* bq = (const float*)d_in[2];
    const float* Wk = (const float*)d_in[3];
    const float* bk = (const float*)d_in[4];
    const float* Wv = (const float*)d_in[5];
    const float* bv = (const float*)d_in[6];
    const float* Wo = (const float*)d_in[7];
    const float* bo = (const float*)d_in[8];

    float* out   = (float*)d_out;
    float* osum  = out  + (size_t)Bb * Ss * Dd;
    float* omask = osum + (size_t)Bb * Ss * Ss;

    float *q, *k, *v, *m, *rsp;
    __half* e;
    __nv_bfloat16 *qhi, *qlo, *khi, *klo, *xhi, *xlo, *mhi, *mlo, *whi, *wlo;
    cudaGetSymbolAddress((void**)&q,   g_q);
    cudaGetSymbolAddress((void**)&k,   g_k);
    cudaGetSymbolAddress((void**)&v,   g_v);
    cudaGetSymbolAddress((void**)&m,   g_m);
    cudaGetSymbolAddress((void**)&e,   g_e);
    cudaGetSymbolAddress((void**)&rsp, g_rsp);
    cudaGetSymbolAddress((void**)&qhi, g_qhi);
    cudaGetSymbolAddress((void**)&qlo, g_qlo);
    cudaGetSymbolAddress((void**)&khi, g_khi);
    cudaGetSymbolAddress((void**)&klo, g_klo);
    cudaGetSymbolAddress((void**)&xhi, g_xhi);
    cudaGetSymbolAddress((void**)&xlo, g_xlo);
    cudaGetSymbolAddress((void**)&mhi, g_mhi);
    cudaGetSymbolAddress((void**)&mlo, g_mlo);
    cudaGetSymbolAddress((void**)&whi, g_whi);
    cudaGetSymbolAddress((void**)&wlo, g_wlo);

    const int NX = Bb * Ss * Dd;
    const int NW = Dd * Dd;

    split4<<<NX/4/256, 256>>>((const float4*)x, (__nv_bfloat162*)xhi,
                              (__nv_bfloat162*)xlo, NX/4);
    split4w<<<dim3(NW/4/256, 1, 4), 256>>>((const float4*)Wq, (const float4*)Wk,
                                           (const float4*)Wv, (const float4*)Wo,
                                           (__nv_bfloat162*)whi, (__nv_bfloat162*)wlo,
                                           NW/4);

    cudaFuncSetAttribute(gemm_qkv, cudaFuncAttributeMaxDynamicSharedMemorySize, GEMM_SMEM);
    cudaFuncSetAttribute(gemm_o,   cudaFuncAttributeMaxDynamicSharedMemorySize, GEMM_SMEM);
    gemm_qkv<<<dim3(Dd/128, Bb*Ss/128, 3), 256, GEMM_SMEM>>>(
        xhi, xlo, whi, wlo, bq, bk, bv, q, k, v, qhi, qlo, khi, klo, Dd, Dd);

    cudaFuncSetAttribute(score_gemm, cudaFuncAttributeMaxDynamicSharedMemorySize, SG_SMEM);
    score_gemm<<<dim3(Ss/128, Ss/128, Bb*Hh), 256, SG_SMEM>>>(
        qhi, qlo, khi, klo, e, rsp);

    attn_stream<<<Bb * Ss / TQ, NT>>>(e, rsp, v, m, osum, omask);

    split4<<<NX/4/256, 256>>>((const float4*)m, (__nv_bfloat162*)mhi,
                              (__nv_bfloat162*)mlo, NX/4);
    gemm_o<<<dim3(Dd/128, Bb*Ss/128), 256, GEMM_SMEM>>>(
        mhi, mlo, whi + 3*(size_t)NW, wlo + 3*(size_t)NW, bo, out, Dd, Dd);
}

// round 14
// speedup vs baseline: 1.0002x; 1.0002x over previous
#include <cuda_runtime.h>
#include <cuda_bf16.h>
#include <cuda_fp16.h>
#include <cstdint>
#include <math.h>

#define Bb 2
#define Ss 2048
#define Dd 1024
#define Hh 16
#define DKk 64
#define TQ 16
#define NT 512
#define TH 0.1f

// ---------------- scratch (__device__ globals; no allocs allowed) ----------
__device__ float g_q [Bb*Ss*Dd];
__device__ float g_k [Bb*Ss*Dd];
__device__ float g_v [Bb*Ss*Dd];
__device__ float g_m [Bb*Ss*Dd];
__device__ __nv_bfloat16 g_qhi[Bb*Ss*Dd], g_qlo[Bb*Ss*Dd];
__device__ __nv_bfloat16 g_khi[Bb*Ss*Dd], g_klo[Bb*Ss*Dd];
__device__ __nv_bfloat16 g_xhi[Bb*Ss*Dd], g_xlo[Bb*Ss*Dd];
__device__ __nv_bfloat16 g_mhi[Bb*Ss*Dd], g_mlo[Bb*Ss*Dd];
__device__ __nv_bfloat16 g_whi[4*Dd*Dd],  g_wlo[4*Dd*Dd];
__device__ __half g_e[(size_t)Bb*Hh*Ss*Ss];          // exp'd scores, 268 MB
__device__ float  g_rsp[(size_t)Bb*Hh*Ss*16];        // partial row sums, 4 MB

extern __shared__ char smraw[];

// ---------------- mma.sync / cp.async helpers (base ISA) -------------------
__device__ __forceinline__ uint32_t smem_u32(const void* p) {
    uint32_t a;
    asm("{ .reg .u64 t; cvta.to.shared.u64 t, %1; cvt.u32.u64 %0, t; }" : "=r"(a) : "l"(p));
    return a;
}
__device__ __forceinline__ void ldsm_x4(uint32_t& r0, uint32_t& r1, uint32_t& r2,
                                        uint32_t& r3, uint32_t addr) {
    asm volatile("ldmatrix.sync.aligned.m8n8.x4.shared.b16 {%0,%1,%2,%3}, [%4];"
                 : "=r"(r0), "=r"(r1), "=r"(r2), "=r"(r3) : "r"(addr));
}
__device__ __forceinline__ void ldsm_x2(uint32_t& r0, uint32_t& r1, uint32_t addr) {
    asm volatile("ldmatrix.sync.aligned.m8n8.x2.shared.b16 {%0,%1}, [%2];"
                 : "=r"(r0), "=r"(r1) : "r"(addr));
}
__device__ __forceinline__ void mma_bf16(float* d, const uint32_t* a, const uint32_t* b) {
    asm volatile(
        "mma.sync.aligned.m16n8k16.row.col.f32.bf16.bf16.f32 "
        "{%0,%1,%2,%3}, {%4,%5,%6,%7}, {%8,%9}, {%0,%1,%2,%3};"
        : "+f"(d[0]), "+f"(d[1]), "+f"(d[2]), "+f"(d[3])
        : "r"(a[0]), "r"(a[1]), "r"(a[2]), "r"(a[3]), "r"(b[0]), "r"(b[1]));
}
__device__ __forceinline__ void cp16(uint32_t saddr, const void* gaddr) {
    asm volatile("cp.async.cg.shared.global [%0], [%1], 16;"
                 :: "r"(saddr), "l"(gaddr) : "memory");
}
#define CP_COMMIT() asm volatile("cp.async.commit_group;" ::: "memory")
#define CP_WAIT(n)  asm volatile("cp.async.wait_group %0;" :: "n"(n) : "memory")

// ---------------------------------------------------------------------------
// splits
// ---------------------------------------------------------------------------
__device__ __forceinline__ void split_one(float4 v, __nv_bfloat162* hi,
                                          __nv_bfloat162* lo, int i) {
    __nv_bfloat16 hx = __float2bfloat16(v.x);
    __nv_bfloat16 hy = __float2bfloat16(v.y);
    __nv_bfloat16 hz = __float2bfloat16(v.z);
    __nv_bfloat16 hw = __float2bfloat16(v.w);
    hi[2*i]   = __halves2bfloat162(hx, hy);
    hi[2*i+1] = __halves2bfloat162(hz, hw);
    lo[2*i]   = __halves2bfloat162(__float2bfloat16(v.x - __bfloat162float(hx)),
                                   __float2bfloat16(v.y - __bfloat162float(hy)));
    lo[2*i+1] = __halves2bfloat162(__float2bfloat16(v.z - __bfloat162float(hz)),
                                   __float2bfloat16(v.w - __bfloat162float(hw)));
}

__global__ __launch_bounds__(256) void split4(
    const float4* __restrict__ x, __nv_bfloat162* __restrict__ hi,
    __nv_bfloat162* __restrict__ lo, int n4)
{
    int i = blockIdx.x * 256 + threadIdx.x;
    if (i >= n4) return;
    split_one(x[i], hi, lo, i);
}

__global__ __launch_bounds__(256) void split4w(
    const float4* __restrict__ w0, const float4* __restrict__ w1,
    const float4* __restrict__ w2, const float4* __restrict__ w3,
    __nv_bfloat162* __restrict__ hi, __nv_bfloat162* __restrict__ lo, int n4)
{
    int z = blockIdx.z;
    const float4* src = (z == 0) ? w0 : (z == 1) ? w1 : (z == 2) ? w2 : w3;
    int i = blockIdx.x * 256 + threadIdx.x;
    if (i >= n4) return;
    split_one(src[i], hi + (size_t)z * n4 * 2, lo + (size_t)z * n4 * 2, i);
}

// ---------------------------------------------------------------------------
// HMMA GEMM body (cp.async double buffer) — projections.
// ---------------------------------------------------------------------------
#define SROW 40
#define STAGE_B (4 * 128 * SROW * 2)
#define A_HI_B  0
#define A_LO_B  (128 * SROW * 2)
#define B_HI_B  (2 * 128 * SROW * 2)
#define B_LO_B  (3 * 128 * SROW * 2)
#define GEMM_SMEM (2 * STAGE_B)

__device__ __forceinline__ void gemm_body(
    const __nv_bfloat16* __restrict__ Ahi, const __nv_bfloat16* __restrict__ Alo,
    const __nv_bfloat16* __restrict__ Whi, const __nv_bfloat16* __restrict__ Wlo,
    const float* __restrict__ bias, float* __restrict__ C,
    __nv_bfloat16* __restrict__ Chi, __nv_bfloat16* __restrict__ Clo,
    int Kdim, int Ndim)
{
    const uint32_t sbase = smem_u32(smraw);
    const int tid = threadIdx.x, lane = tid & 31, wid = tid >> 5;
    const int wm = (wid >> 2) * 64;
    const int wn = (wid & 3) * 32;
    const int n0 = blockIdx.x * 128, m0 = blockIdx.y * 128;

    uint32_t aoff[4], boff[4];
    #pragma unroll
    for (int mt = 0; mt < 4; ++mt)
        aoff[mt] = ((wm + mt * 16 + (lane & 15)) * SROW + (lane >> 4) * 8) * 2;
    #pragma unroll
    for (int nt = 0; nt < 4; ++nt)
        boff[nt] = ((wn + nt * 8 + (lane & 7)) * SROW + ((lane >> 3) & 1) * 8) * 2;

    const int r0 = tid >> 2,          c0 = (tid & 3) * 8;
    const int r1 = (tid + 256) >> 2,  c1 = ((tid + 256) & 3) * 8;
    const uint32_t s_off0 = (uint32_t)(r0 * SROW + c0) * 2;
    const uint32_t s_off1 = (uint32_t)(r1 * SROW + c1) * 2;

    const __nv_bfloat16* ga0h = Ahi + (size_t)(m0 + r0) * Kdim + c0;
    const __nv_bfloat16* ga1h = Ahi + (size_t)(m0 + r1) * Kdim + c1;
    const __nv_bfloat16* ga0l = Alo + (size_t)(m0 + r0) * Kdim + c0;
    const __nv_bfloat16* ga1l = Alo + (size_t)(m0 + r1) * Kdim + c1;
    const __nv_bfloat16* gb0h = Whi + (size_t)(n0 + r0) * Kdim + c0;
    const __nv_bfloat16* gb1h = Whi + (size_t)(n0 + r1) * Kdim + c1;
    const __nv_bfloat16* gb0l = Wlo + (size_t)(n0 + r0) * Kdim + c0;
    const __nv_bfloat16* gb1l = Wlo + (size_t)(n0 + r1) * Kdim + c1;

    float d[4][4][4];
    #pragma unroll
    for (int mt = 0; mt < 4; ++mt)
        #pragma unroll
        for (int nt = 0; nt < 4; ++nt)
            #pragma unroll
            for (int i = 0; i < 4; ++i) d[mt][nt][i] = 0.f;

    const int nkt = Kdim >> 5;

    auto load_stage = [&](int stg, int kt) {
        const int kb = kt << 5;
        const uint32_t s = sbase + (uint32_t)stg * STAGE_B;
        cp16(s + A_HI_B + s_off0, ga0h + kb);
        cp16(s + A_HI_B + s_off1, ga1h + kb);
        cp16(s + A_LO_B + s_off0, ga0l + kb);
        cp16(s + A_LO_B + s_off1, ga1l + kb);
        cp16(s + B_HI_B + s_off0, gb0h + kb);
        cp16(s + B_HI_B + s_off1, gb1h + kb);
        cp16(s + B_LO_B + s_off0, gb0l + kb);
        cp16(s + B_LO_B + s_off1, gb1l + kb);
        CP_COMMIT();
    };

    load_stage(0, 0);

    for (int kt = 0; kt < nkt; ++kt) {
        if (kt + 1 < nkt) { load_stage((kt + 1) & 1, kt + 1); CP_WAIT(1); }
        else              { CP_WAIT(0); }
        __syncthreads();

        const uint32_t s = sbase + (uint32_t)(kt & 1) * STAGE_B;
        #pragma unroll
        for (int ks = 0; ks < 2; ++ks) {
            const uint32_t kadd = ks * 32;
            uint32_t ah[4][4], al[4][4], bh[4][2], bl[4][2];
            #pragma unroll
            for (int mt = 0; mt < 4; ++mt) {
                ldsm_x4(ah[mt][0], ah[mt][1], ah[mt][2], ah[mt][3],
                        s + A_HI_B + aoff[mt] + kadd);
                ldsm_x4(al[mt][0], al[mt][1], al[mt][2], al[mt][3],
                        s + A_LO_B + aoff[mt] + kadd);
            }
            #pragma unroll
            for (int nt = 0; nt < 4; ++nt) {
                ldsm_x2(bh[nt][0], bh[nt][1], s + B_HI_B + boff[nt] + kadd);
                ldsm_x2(bl[nt][0], bl[nt][1], s + B_LO_B + boff[nt] + kadd);
            }
            #pragma unroll
            for (int mt = 0; mt < 4; ++mt)
                #pragma unroll
                for (int nt = 0; nt < 4; ++nt) {
                    mma_bf16(d[mt][nt], ah[mt], bh[nt]);
                    mma_bf16(d[mt][nt], ah[mt], bl[nt]);
                    mma_bf16(d[mt][nt], al[mt], bh[nt]);
                }
        }
        __syncthreads();
    }

    const int g = lane >> 2, c2 = (lane & 3) * 2;
    #pragma unroll
    for (int mt = 0; mt < 4; ++mt) {
        #pragma unroll
        for (int nt = 0; nt < 4; ++nt) {
            int m = m0 + wm + mt * 16 + g;
            int n = n0 + wn + nt * 8 + c2;
            float bx = bias[n], by = bias[n + 1];
            float2 o0 = make_float2(d[mt][nt][0] + bx, d[mt][nt][1] + by);
            float2 o1 = make_float2(d[mt][nt][2] + bx, d[mt][nt][3] + by);
            *(float2*)(C + (size_t)m * Ndim + n) = o0;
            *(float2*)(C + (size_t)(m + 8) * Ndim + n) = o1;
            if (Chi) {
                __nv_bfloat16 h0x = __float2bfloat16(o0.x), h0y = __float2bfloat16(o0.y);
                __nv_bfloat16 h1x = __float2bfloat16(o1.x), h1y = __float2bfloat16(o1.y);
                size_t i0 = (size_t)m * Ndim + n, i1 = (size_t)(m + 8) * Ndim + n;
                Chi[i0] = h0x; Chi[i0 + 1] = h0y;
                Chi[i1] = h1x; Chi[i1 + 1] = h1y;
                Clo[i0]     = __float2bfloat16(o0.x - __bfloat162float(h0x));
                Clo[i0 + 1] = __float2bfloat16(o0.y - __bfloat162float(h0y));
                Clo[i1]     = __float2bfloat16(o1.x - __bfloat162float(h1x));
                Clo[i1 + 1] = __float2bfloat16(o1.y - __bfloat162float(h1y));
            }
        }
    }
}

__global__ __launch_bounds__(256, 2)
void gemm_qkv(const __nv_bfloat16* __restrict__ Ahi, const __nv_bfloat16* __restrict__ Alo,
              const __nv_bfloat16* __restrict__ Whi, const __nv_bfloat16* __restrict__ Wlo,
              const float* bq, const float* bk, const float* bv,
              float* Cq, float* Ck, float* Cv,
              __nv_bfloat16* qhi, __nv_bfloat16* qlo,
              __nv_bfloat16* khi, __nv_bfloat16* klo,
              int Kdim, int Ndim)
{
    const int z = blockIdx.z;
    const size_t NW = (size_t)Kdim * Ndim;
    const float* bias = (z == 0) ? bq : (z == 1) ? bk : bv;
    float* C = (z == 0) ? Cq : (z == 1) ? Ck : Cv;
    __nv_bfloat16* Chi = (z == 0) ? qhi : (z == 1) ? khi : (__nv_bfloat16*)nullptr;
    __nv_bfloat16* Clo = (z == 0) ? qlo : (z == 1) ? klo : (__nv_bfloat16*)nullptr;
    gemm_body(Ahi, Alo, Whi + z * NW, Wlo + z * NW, bias, C, Chi, Clo, Kdim, Ndim);
}

__global__ __launch_bounds__(256, 2)
void gemm_o(const __nv_bfloat16* __restrict__ Ahi, const __nv_bfloat16* __restrict__ Alo,
            const __nv_bfloat16* __restrict__ Whi, const __nv_bfloat16* __restrict__ Wlo,
            const float* __restrict__ bias, float* __restrict__ C, int Kdim, int Ndim)
{
    gemm_body(Ahi, Alo, Whi, Wlo, bias, C, nullptr, nullptr, Kdim, Ndim);
}

// ---------------------------------------------------------------------------
// fast exp (FMA pipe only)
// ---------------------------------------------------------------------------
__device__ __forceinline__ float fexp(float x) {
    x = fmaxf(x, -87.0f);
    float p = x * 1.44269504088896340f;
    int   ni = __float2int_rn(p);
    float f  = p - (float)ni;
    float t  = f * 0.69314718055994531f;
    float r  = 1.9841269841269841e-4f;
    r = fmaf(r, t, 1.3888888888888889e-3f);
    r = fmaf(r, t, 8.3333333333333333e-3f);
    r = fmaf(r, t, 4.1666666666666664e-2f);
    r = fmaf(r, t, 1.6666666666666666e-1f);
    r = fmaf(r, t, 0.5f);
    r = fmaf(r, t, 1.0f);
    r = fmaf(r, t, 1.0f);
    return r * __int_as_float((ni + 127) << 23);
}

// ---------------------------------------------------------------------------
// score_gemm: E[b,h,q,k] = exp(Q·K^T / 8) in fp16 + per-tile partial row sums.
// One 128x128 tile per block, K=64 single-shot, split-bf16 3-pass HMMA.
// grid (16 ktile, 16 qtile, 32 bh), 256 threads, 2 CTAs/SM.
// ---------------------------------------------------------------------------
#define KSTR 72
#define SA_HI 0
#define SA_LO 18432
#define SB_HI 36864
#define SB_LO 55296
#define RS_O  73728
#define SG_SMEM (73728 + 512)

__global__ __launch_bounds__(256, 2)
void score_gemm(const __nv_bfloat16* __restrict__ QHI, const __nv_bfloat16* __restrict__ QLO,
                const __nv_bfloat16* __restrict__ KHI, const __nv_bfloat16* __restrict__ KLO,
                __half* __restrict__ E, float* __restrict__ rsp)
{
    char* smb = smraw;
    const uint32_t sbase = smem_u32(smb);
    const int tid = threadIdx.x, lane = tid & 31, wid = tid >> 5;
    const int k0 = blockIdx.x * 128, q0 = blockIdx.y * 128;
    const int z = blockIdx.z;                  // b*16 + h
    const int b = z >> 4, h = z & 15;

    const __nv_bfloat16* Qh = QHI + ((size_t)b * Ss + q0) * Dd + h * DKk;
    const __nv_bfloat16* Ql = QLO + ((size_t)b * Ss + q0) * Dd + h * DKk;
    const __nv_bfloat16* Kh = KHI + ((size_t)b * Ss + k0) * Dd + h * DKk;
    const __nv_bfloat16* Kl = KLO + ((size_t)b * Ss + k0) * Dd + h * DKk;

    // load 128x64 tiles (hi+lo for Q and K)
    #pragma unroll
    for (int s = 0; s < 4; ++s) {
        int slot = tid + s * 256;
        int row = slot >> 3, c = (slot & 7) * 8;
        size_t go = (size_t)row * Dd + c;
        uint32_t so = (uint32_t)(row * KSTR + c) * 2;
        cp16(sbase + SA_HI + so, Qh + go);
        cp16(sbase + SA_LO + so, Ql + go);
        cp16(sbase + SB_HI + so, Kh + go);
        cp16(sbase + SB_LO + so, Kl + go);
    }
    CP_COMMIT();
    CP_WAIT(0);
    __syncthreads();

    const int wm = (wid >> 2) * 64;
    const int wn = (wid & 3) * 32;
    uint32_t aoff[4], boff[4];
    #pragma unroll
    for (int mt = 0; mt < 4; ++mt)
        aoff[mt] = ((wm + mt * 16 + (lane & 15)) * KSTR + (lane >> 4) * 8) * 2;
    #pragma unroll
    for (int nt = 0; nt < 4; ++nt)
        boff[nt] = ((wn + nt * 8 + (lane & 7)) * KSTR + ((lane >> 3) & 1) * 8) * 2;

    float d[4][4][4];
    #pragma unroll
    for (int mt = 0; mt < 4; ++mt)
        #pragma unroll
        for (int nt = 0; nt < 4; ++nt)
            #pragma unroll
            for (int i = 0; i < 4; ++i) d[mt][nt][i] = 0.f;

    #pragma unroll
    for (int kk = 0; kk < 4; ++kk) {
        const uint32_t kadd = kk * 32;
        uint32_t ah[4][4], al[4][4], bh[4][2], bl[4][2];
        #pragma unroll
        for (int mt = 0; mt < 4; ++mt) {
            ldsm_x4(ah[mt][0], ah[mt][1], ah[mt][2], ah[mt][3],
                    sbase + SA_HI + aoff[mt] + kadd);
            ldsm_x4(al[mt][0], al[mt][1], al[mt][2], al[mt][3],
                    sbase + SA_LO + aoff[mt] + kadd);
        }
        #pragma unroll
        for (int nt = 0; nt < 4; ++nt) {
            ldsm_x2(bh[nt][0], bh[nt][1], sbase + SB_HI + boff[nt] + kadd);
            ldsm_x2(bl[nt][0], bl[nt][1], sbase + SB_LO + boff[nt] + kadd);
        }
        #pragma unroll
        for (int mt = 0; mt < 4; ++mt)
            #pragma unroll
            for (int nt = 0; nt < 4; ++nt) {
                mma_bf16(d[mt][nt], ah[mt], bh[nt]);
                mma_bf16(d[mt][nt], ah[mt], bl[nt]);
                mma_bf16(d[mt][nt], al[mt], bh[nt]);
            }
    }

    // epilogue: exp, fp16 store, per-tile row sums (deterministic)
    __syncthreads();
    float* rs = (float*)(smb + RS_O);
    if (tid < 128) rs[tid] = 0.f;
    __syncthreads();

    const int g = lane >> 2, c2 = (lane & 3) * 2;
    __half* Eb = E + ((size_t)z * Ss + q0) * Ss + k0;
    #pragma unroll
    for (int mt = 0; mt < 4; ++mt) {
        float r0 = 0.f, r1 = 0.f;
        const int rowA = wm + mt * 16 + g;
        #pragma unroll
        for (int nt = 0; nt < 4; ++nt) {
            int col = wn + nt * 8 + c2;
            float e0 = fexp(d[mt][nt][0] * 0.125f);
            float e1 = fexp(d[mt][nt][1] * 0.125f);
            float e2 = fexp(d[mt][nt][2] * 0.125f);
            float e3 = fexp(d[mt][nt][3] * 0.125f);
            *(__half2*)(Eb + (size_t)rowA * Ss + col)       = __floats2half2_rn(e0, e1);
            *(__half2*)(Eb + (size_t)(rowA + 8) * Ss + col) = __floats2half2_rn(e2, e3);
            r0 += e0 + e1;
            r1 += e2 + e3;
        }
        r0 += __shfl_xor_sync(0xffffffffu, r0, 1);
        r0 += __shfl_xor_sync(0xffffffffu, r0, 2);
        r1 += __shfl_xor_sync(0xffffffffu, r1, 1);
        r1 += __shfl_xor_sync(0xffffffffu, r1, 2);
        if ((lane & 3) == 0) {
            atomicAdd(&rs[rowA], r0);
            atomicAdd(&rs[rowA + 8], r1);
        }
    }
    __syncthreads();
    if (tid < 128)
        rsp[((size_t)z * Ss + q0 + tid) * 16 + blockIdx.x] = rs[tid];
}

// ---------------------------------------------------------------------------
// attn_stream: per (b, 16 q-rows) block; per head: inv from partials, one
// coalesced fp16 pass over E accumulating psum/pmask; rare PV path from E.
// ---------------------------------------------------------------------------
__global__ __launch_bounds__(NT)
void attn_stream(const __half* __restrict__ E, const float* __restrict__ rsp,
                 const float* __restrict__ V, float* __restrict__ merged,
                 float* __restrict__ osum, float* __restrict__ omask)
{
    __shared__ float sm_inv[16];
    const int tid  = threadIdx.x;
    const int lane = tid & 31;
    const int wid  = tid >> 5;
    const int b    = blockIdx.x >> 7;
    const int q0   = (blockIdx.x & 127) * TQ;
    const float* Vb = V + (size_t)b * Ss * Dd;

    float4   psum[TQ];
    uint32_t pm[TQ];
    #pragma unroll
    for (int q = 0; q < TQ; ++q) {
        psum[q] = make_float4(0.f, 0.f, 0.f, 0.f);
        pm[q] = 0u;
    }

    for (int h = 0; h < Hh; ++h) {
        const int z = b * Hh + h;
        const int hd = h * DKk;
        const __half* Eb = E + ((size_t)z * Ss + q0) * Ss;

        __syncthreads();                         // sm_inv reuse guard
        if (tid < 16) {
            const float* rp = rsp + ((size_t)z * Ss + q0 + tid) * 16;
            float s = 0.f;
            #pragma unroll
            for (int i = 0; i < 16; ++i) s += rp[i];
            sm_inv[tid] = 1.0f / s;
        }
        __syncthreads();
        float invf[TQ];
        #pragma unroll
        for (int q = 0; q < TQ; ++q) invf[q] = sm_inv[q];

        uint32_t anyk = 0;
        #pragma unroll
        for (int q = 0; q < TQ; ++q) {
            uint2 uu = *(const uint2*)(Eb + (size_t)q * Ss + tid * 4);
            float2 f01 = __half22float2(*reinterpret_cast<__half2*>(&uu.x));
            float2 f23 = __half22float2(*reinterpret_cast<__half2*>(&uu.y));
            float4 p4;
            p4.x = f01.x * invf[q]; p4.y = f01.y * invf[q];
            p4.z = f23.x * invf[q]; p4.w = f23.y * invf[q];
            uint32_t u = (p4.x >= TH ? 0x1u : 0u) | (p4.y >= TH ? 0x100u : 0u) |
                         (p4.z >= TH ? 0x10000u : 0u) | (p4.w >= TH ? 0x1000000u : 0u);
            pm[q] += u;
            anyk |= u;
            psum[q].x += p4.x; psum[q].y += p4.y;
            psum[q].z += p4.z; psum[q].w += p4.w;
        }
        int any = __syncthreads_or((int)anyk);

        if (any) {
            const float inv = sm_inv[wid];
            const __half* srow = Eb + (size_t)wid * Ss;
            const float* vb2 = Vb + hd + lane * 2;
            float2 ctx = make_float2(0.f, 0.f);
            for (int k = 0; k < Ss; ++k) {
                float p = __half2float(srow[k]) * inv;
                p = (p >= TH) ? p : 0.f;
                float2 vv = *(const float2*)(vb2 + (size_t)k * Dd);
                ctx.x = fmaf(p, vv.x, ctx.x);
                ctx.y = fmaf(p, vv.y, ctx.y);
            }
            *(float2*)(merged + ((size_t)b * Ss + q0 + wid) * Dd + hd + lane * 2) = ctx;
        } else {
            *(float2*)(merged + ((size_t)b * Ss + q0 + wid) * Dd + hd + lane * 2) =
                make_float2(0.f, 0.f);
        }
    }

    #pragma unroll
    for (int q = 0; q < TQ; ++q) {
        size_t row = (size_t)b * Ss + q0 + q;
        ((float4*)(osum + row * Ss))[tid] = psum[q];
        uint32_t u = pm[q];
        float4 f;
        f.x = (float)(u & 255u);
        f.y = (float)((u >> 8) & 255u);
        f.z = (float)((u >> 16) & 255u);
        f.w = (float)(u >> 24);
        ((float4*)(omask + row * Ss))[tid] = f;
    }
}

// ---------------------------------------------------------------------------
extern "C" void kernel_launch(void* const* d_in, const int* in_sizes, int n_in,
                              void* d_out, int out_size)
{
    const float* x  = (const float*)d_in[0];
    const float* Wq = (const float*)d_in[1];
    const float* bq = (const float*)d_in[2];
    const float* Wk = (const float*)d_in[3];
    const float* bk = (const float*)d_in[4];
    const float* Wv = (const float*)d_in[5];
    const float* bv = (const float*)d_in[6];
    const float* Wo = (const float*)d_in[7];
    const float* bo = (const float*)d_in[8];

    float* out   = (float*)d_out;
    float* osum  = out  + (size_t)Bb * Ss * Dd;
    float* omask = osum + (size_t)Bb * Ss * Ss;

    float *q, *k, *v, *m, *rsp;
    __half* e;
    __nv_bfloat16 *qhi, *qlo, *khi, *klo, *xhi, *xlo, *mhi, *mlo, *whi, *wlo;
    cudaGetSymbolAddress((void**)&q,   g_q);
    cudaGetSymbolAddress((void**)&k,   g_k);
    cudaGetSymbolAddress((void**)&v,   g_v);
    cudaGetSymbolAddress((void**)&m,   g_m);
    cudaGetSymbolAddress((void**)&e,   g_e);
    cudaGetSymbolAddress((void**)&rsp, g_rsp);
    cudaGetSymbolAddress((void**)&qhi, g_qhi);
    cudaGetSymbolAddress((void**)&qlo, g_qlo);
    cudaGetSymbolAddress((void**)&khi, g_khi);
    cudaGetSymbolAddress((void**)&klo, g_klo);
    cudaGetSymbolAddress((void**)&xhi, g_xhi);
    cudaGetSymbolAddress((void**)&xlo, g_xlo);
    cudaGetSymbolAddress((void**)&mhi, g_mhi);
    cudaGetSymbolAddress((void**)&mlo, g_mlo);
    cudaGetSymbolAddress((void**)&whi, g_whi);
    cudaGetSymbolAddress((void**)&wlo, g_wlo);

    const int NX = Bb * Ss * Dd;
    const int NW = Dd * Dd;

    split4<<<NX/4/256, 256>>>((const float4*)x, (__nv_bfloat162*)xhi,
                              (__nv_bfloat162*)xlo, NX/4);
    split4w<<<dim3(NW/4/256, 1, 4), 256>>>((const float4*)Wq, (const float4*)Wk,
                                           (const float4*)Wv, (const float4*)Wo,
                                           (__nv_bfloat162*)whi, (__nv_bfloat162*)wlo,
                                           NW/4);

    cudaFuncSetAttribute(gemm_qkv, cudaFuncAttributeMaxDynamicSharedMemorySize, GEMM_SMEM);
    cudaFuncSetAttribute(gemm_o,   cudaFuncAttributeMaxDynamicSharedMemorySize, GEMM_SMEM);
    gemm_qkv<<<dim3(Dd/128, Bb*Ss/128, 3), 256, GEMM_SMEM>>>(
        xhi, xlo, whi, wlo, bq, bk, bv, q, k, v, qhi, qlo, khi, klo, Dd, Dd);

    cudaFuncSetAttribute(score_gemm, cudaFuncAttributeMaxDynamicSharedMemorySize, SG_SMEM);
    score_gemm<<<dim3(Ss/128, Ss/128, Bb*Hh), 256, SG_SMEM>>>(
        qhi, qlo, khi, klo, e, rsp);

    attn_stream<<<Bb * Ss / TQ, NT>>>(e, rsp, v, m, osum, omask);

    split4<<<NX/4/256, 256>>>((const float4*)m, (__nv_bfloat162*)mhi,
                              (__nv_bfloat162*)mlo, NX/4);
    gemm_o<<<dim3(Dd/128, Bb*Ss/128), 256, GEMM_SMEM>>>(
        mhi, mlo, whi + 3*(size_t)NW, wlo + 3*(size_t)NW, bo, out, Dd, Dd);
}

// round 15
// speedup vs baseline: 1.0016x; 1.0014x over previous
#include <cuda_runtime.h>
#include <cuda_bf16.h>
#include <cuda_fp16.h>
#include <cstdint>
#include <math.h>

#define Bb 2
#define Ss 2048
#define Dd 1024
#define Hh 16
#define DKk 64
#define TQ 16
#define NT 512
#define TH 0.1f

// ---------------- scratch (__device__ globals; no allocs allowed) ----------
__device__ float g_q [Bb*Ss*Dd];
__device__ float g_k [Bb*Ss*Dd];
__device__ float g_v [Bb*Ss*Dd];
__device__ float g_m [Bb*Ss*Dd];
__device__ __nv_bfloat16 g_qhi[Bb*Ss*Dd], g_qlo[Bb*Ss*Dd];
__device__ __nv_bfloat16 g_khi[Bb*Ss*Dd], g_klo[Bb*Ss*Dd];
__device__ __nv_bfloat16 g_xhi[Bb*Ss*Dd], g_xlo[Bb*Ss*Dd];
__device__ __nv_bfloat16 g_mhi[Bb*Ss*Dd], g_mlo[Bb*Ss*Dd];
__device__ __nv_bfloat16 g_whi[4*Dd*Dd],  g_wlo[4*Dd*Dd];
__device__ __half g_e[(size_t)Bb*Hh*Ss*Ss];          // exp'd scores, 268 MB
__device__ float  g_rsp[(size_t)Bb*Hh*Ss*16];        // partial row sums, 4 MB

extern __shared__ char smraw[];

// ---------------- mma.sync / cp.async helpers (base ISA) -------------------
__device__ __forceinline__ uint32_t smem_u32(const void* p) {
    uint32_t a;
    asm("{ .reg .u64 t; cvta.to.shared.u64 t, %1; cvt.u32.u64 %0, t; }" : "=r"(a) : "l"(p));
    return a;
}
__device__ __forceinline__ void ldsm_x4(uint32_t& r0, uint32_t& r1, uint32_t& r2,
                                        uint32_t& r3, uint32_t addr) {
    asm volatile("ldmatrix.sync.aligned.m8n8.x4.shared.b16 {%0,%1,%2,%3}, [%4];"
                 : "=r"(r0), "=r"(r1), "=r"(r2), "=r"(r3) : "r"(addr));
}
__device__ __forceinline__ void ldsm_x2(uint32_t& r0, uint32_t& r1, uint32_t addr) {
    asm volatile("ldmatrix.sync.aligned.m8n8.x2.shared.b16 {%0,%1}, [%2];"
                 : "=r"(r0), "=r"(r1) : "r"(addr));
}
__device__ __forceinline__ void mma_bf16(float* d, const uint32_t* a, const uint32_t* b) {
    asm volatile(
        "mma.sync.aligned.m16n8k16.row.col.f32.bf16.bf16.f32 "
        "{%0,%1,%2,%3}, {%4,%5,%6,%7}, {%8,%9}, {%0,%1,%2,%3};"
        : "+f"(d[0]), "+f"(d[1]), "+f"(d[2]), "+f"(d[3])
        : "r"(a[0]), "r"(a[1]), "r"(a[2]), "r"(a[3]), "r"(b[0]), "r"(b[1]));
}
__device__ __forceinline__ void cp16(uint32_t saddr, const void* gaddr) {
    asm volatile("cp.async.cg.shared.global [%0], [%1], 16;"
                 :: "r"(saddr), "l"(gaddr) : "memory");
}
#define CP_COMMIT() asm volatile("cp.async.commit_group;" ::: "memory")
#define CP_WAIT(n)  asm volatile("cp.async.wait_group %0;" :: "n"(n) : "memory")

// ---------------------------------------------------------------------------
// splits
// ---------------------------------------------------------------------------
__device__ __forceinline__ void split_one(float4 v, __nv_bfloat162* hi,
                                          __nv_bfloat162* lo, int i) {
    __nv_bfloat16 hx = __float2bfloat16(v.x);
    __nv_bfloat16 hy = __float2bfloat16(v.y);
    __nv_bfloat16 hz = __float2bfloat16(v.z);
    __nv_bfloat16 hw = __float2bfloat16(v.w);
    hi[2*i]   = __halves2bfloat162(hx, hy);
    hi[2*i+1] = __halves2bfloat162(hz, hw);
    lo[2*i]   = __halves2bfloat162(__float2bfloat16(v.x - __bfloat162float(hx)),
                                   __float2bfloat16(v.y - __bfloat162float(hy)));
    lo[2*i+1] = __halves2bfloat162(__float2bfloat16(v.z - __bfloat162float(hz)),
                                   __float2bfloat16(v.w - __bfloat162float(hw)));
}

__global__ __launch_bounds__(256) void split4(
    const float4* __restrict__ x, __nv_bfloat162* __restrict__ hi,
    __nv_bfloat162* __restrict__ lo, int n4)
{
    int i = blockIdx.x * 256 + threadIdx.x;
    if (i >= n4) return;
    split_one(x[i], hi, lo, i);
}

__global__ __launch_bounds__(256) void split4w(
    const float4* __restrict__ w0, const float4* __restrict__ w1,
    const float4* __restrict__ w2, const float4* __restrict__ w3,
    __nv_bfloat162* __restrict__ hi, __nv_bfloat162* __restrict__ lo, int n4)
{
    int z = blockIdx.z;
    const float4* src = (z == 0) ? w0 : (z == 1) ? w1 : (z == 2) ? w2 : w3;
    int i = blockIdx.x * 256 + threadIdx.x;
    if (i >= n4) return;
    split_one(src[i], hi + (size_t)z * n4 * 2, lo + (size_t)z * n4 * 2, i);
}

// ---------------------------------------------------------------------------
// HMMA GEMM body (cp.async double buffer) — projections.
// ---------------------------------------------------------------------------
#define SROW 40
#define STAGE_B (4 * 128 * SROW * 2)
#define A_HI_B  0
#define A_LO_B  (128 * SROW * 2)
#define B_HI_B  (2 * 128 * SROW * 2)
#define B_LO_B  (3 * 128 * SROW * 2)
#define GEMM_SMEM (2 * STAGE_B)

__device__ __forceinline__ void gemm_body(
    const __nv_bfloat16* __restrict__ Ahi, const __nv_bfloat16* __restrict__ Alo,
    const __nv_bfloat16* __restrict__ Whi, const __nv_bfloat16* __restrict__ Wlo,
    const float* __restrict__ bias, float* __restrict__ C,
    __nv_bfloat16* __restrict__ Chi, __nv_bfloat16* __restrict__ Clo,
    int Kdim, int Ndim)
{
    const uint32_t sbase = smem_u32(smraw);
    const int tid = threadIdx.x, lane = tid & 31, wid = tid >> 5;
    const int wm = (wid >> 2) * 64;
    const int wn = (wid & 3) * 32;
    const int n0 = blockIdx.x * 128, m0 = blockIdx.y * 128;

    uint32_t aoff[4], boff[4];
    #pragma unroll
    for (int mt = 0; mt < 4; ++mt)
        aoff[mt] = ((wm + mt * 16 + (lane & 15)) * SROW + (lane >> 4) * 8) * 2;
    #pragma unroll
    for (int nt = 0; nt < 4; ++nt)
        boff[nt] = ((wn + nt * 8 + (lane & 7)) * SROW + ((lane >> 3) & 1) * 8) * 2;

    const int r0 = tid >> 2,          c0 = (tid & 3) * 8;
    const int r1 = (tid + 256) >> 2,  c1 = ((tid + 256) & 3) * 8;
    const uint32_t s_off0 = (uint32_t)(r0 * SROW + c0) * 2;
    const uint32_t s_off1 = (uint32_t)(r1 * SROW + c1) * 2;

    const __nv_bfloat16* ga0h = Ahi + (size_t)(m0 + r0) * Kdim + c0;
    const __nv_bfloat16* ga1h = Ahi + (size_t)(m0 + r1) * Kdim + c1;
    const __nv_bfloat16* ga0l = Alo + (size_t)(m0 + r0) * Kdim + c0;
    const __nv_bfloat16* ga1l = Alo + (size_t)(m0 + r1) * Kdim + c1;
    const __nv_bfloat16* gb0h = Whi + (size_t)(n0 + r0) * Kdim + c0;
    const __nv_bfloat16* gb1h = Whi + (size_t)(n0 + r1) * Kdim + c1;
    const __nv_bfloat16* gb0l = Wlo + (size_t)(n0 + r0) * Kdim + c0;
    const __nv_bfloat16* gb1l = Wlo + (size_t)(n0 + r1) * Kdim + c1;

    float d[4][4][4];
    #pragma unroll
    for (int mt = 0; mt < 4; ++mt)
        #pragma unroll
        for (int nt = 0; nt < 4; ++nt)
            #pragma unroll
            for (int i = 0; i < 4; ++i) d[mt][nt][i] = 0.f;

    const int nkt = Kdim >> 5;

    auto load_stage = [&](int stg, int kt) {
        const int kb = kt << 5;
        const uint32_t s = sbase + (uint32_t)stg * STAGE_B;
        cp16(s + A_HI_B + s_off0, ga0h + kb);
        cp16(s + A_HI_B + s_off1, ga1h + kb);
        cp16(s + A_LO_B + s_off0, ga0l + kb);
        cp16(s + A_LO_B + s_off1, ga1l + kb);
        cp16(s + B_HI_B + s_off0, gb0h + kb);
        cp16(s + B_HI_B + s_off1, gb1h + kb);
        cp16(s + B_LO_B + s_off0, gb0l + kb);
        cp16(s + B_LO_B + s_off1, gb1l + kb);
        CP_COMMIT();
    };

    load_stage(0, 0);

    for (int kt = 0; kt < nkt; ++kt) {
        if (kt + 1 < nkt) { load_stage((kt + 1) & 1, kt + 1); CP_WAIT(1); }
        else              { CP_WAIT(0); }
        __syncthreads();

        const uint32_t s = sbase + (uint32_t)(kt & 1) * STAGE_B;
        #pragma unroll
        for (int ks = 0; ks < 2; ++ks) {
            const uint32_t kadd = ks * 32;
            uint32_t ah[4][4], al[4][4], bh[4][2], bl[4][2];
            #pragma unroll
            for (int mt = 0; mt < 4; ++mt) {
                ldsm_x4(ah[mt][0], ah[mt][1], ah[mt][2], ah[mt][3],
                        s + A_HI_B + aoff[mt] + kadd);
                ldsm_x4(al[mt][0], al[mt][1], al[mt][2], al[mt][3],
                        s + A_LO_B + aoff[mt] + kadd);
            }
            #pragma unroll
            for (int nt = 0; nt < 4; ++nt) {
                ldsm_x2(bh[nt][0], bh[nt][1], s + B_HI_B + boff[nt] + kadd);
                ldsm_x2(bl[nt][0], bl[nt][1], s + B_LO_B + boff[nt] + kadd);
            }
            #pragma unroll
            for (int mt = 0; mt < 4; ++mt)
                #pragma unroll
                for (int nt = 0; nt < 4; ++nt) {
                    mma_bf16(d[mt][nt], ah[mt], bh[nt]);
                    mma_bf16(d[mt][nt], ah[mt], bl[nt]);
                    mma_bf16(d[mt][nt], al[mt], bh[nt]);
                }
        }
        __syncthreads();
    }

    const int g = lane >> 2, c2 = (lane & 3) * 2;
    #pragma unroll
    for (int mt = 0; mt < 4; ++mt) {
        #pragma unroll
        for (int nt = 0; nt < 4; ++nt) {
            int m = m0 + wm + mt * 16 + g;
            int n = n0 + wn + nt * 8 + c2;
            float bx = bias[n], by = bias[n + 1];
            float2 o0 = make_float2(d[mt][nt][0] + bx, d[mt][nt][1] + by);
            float2 o1 = make_float2(d[mt][nt][2] + bx, d[mt][nt][3] + by);
            *(float2*)(C + (size_t)m * Ndim + n) = o0;
            *(float2*)(C + (size_t)(m + 8) * Ndim + n) = o1;
            if (Chi) {
                __nv_bfloat16 h0x = __float2bfloat16(o0.x), h0y = __float2bfloat16(o0.y);
                __nv_bfloat16 h1x = __float2bfloat16(o1.x), h1y = __float2bfloat16(o1.y);
                size_t i0 = (size_t)m * Ndim + n, i1 = (size_t)(m + 8) * Ndim + n;
                Chi[i0] = h0x; Chi[i0 + 1] = h0y;
                Chi[i1] = h1x; Chi[i1 + 1] = h1y;
                Clo[i0]     = __float2bfloat16(o0.x - __bfloat162float(h0x));
                Clo[i0 + 1] = __float2bfloat16(o0.y - __bfloat162float(h0y));
                Clo[i1]     = __float2bfloat16(o1.x - __bfloat162float(h1x));
                Clo[i1 + 1] = __float2bfloat16(o1.y - __bfloat162float(h1y));
            }
        }
    }
}

__global__ __launch_bounds__(256, 2)
void gemm_qkv(const __nv_bfloat16* __restrict__ Ahi, const __nv_bfloat16* __restrict__ Alo,
              const __nv_bfloat16* __restrict__ Whi, const __nv_bfloat16* __restrict__ Wlo,
              const float* bq, const float* bk, const float* bv,
              float* Cq, float* Ck, float* Cv,
              __nv_bfloat16* qhi, __nv_bfloat16* qlo,
              __nv_bfloat16* khi, __nv_bfloat16* klo,
              int Kdim, int Ndim)
{
    const int z = blockIdx.z;
    const size_t NW = (size_t)Kdim * Ndim;
    const float* bias = (z == 0) ? bq : (z == 1) ? bk : bv;
    float* C = (z == 0) ? Cq : (z == 1) ? Ck : Cv;
    __nv_bfloat16* Chi = (z == 0) ? qhi : (z == 1) ? khi : (__nv_bfloat16*)nullptr;
    __nv_bfloat16* Clo = (z == 0) ? qlo : (z == 1) ? klo : (__nv_bfloat16*)nullptr;
    gemm_body(Ahi, Alo, Whi + z * NW, Wlo + z * NW, bias, C, Chi, Clo, Kdim, Ndim);
}

__global__ __launch_bounds__(256, 2)
void gemm_o(const __nv_bfloat16* __restrict__ Ahi, const __nv_bfloat16* __restrict__ Alo,
            const __nv_bfloat16* __restrict__ Whi, const __nv_bfloat16* __restrict__ Wlo,
            const float* __restrict__ bias, float* __restrict__ C, int Kdim, int Ndim)
{
    gemm_body(Ahi, Alo, Whi, Wlo, bias, C, nullptr, nullptr, Kdim, Ndim);
}

// ---------------------------------------------------------------------------
// fast exp (FMA pipe only)
// ---------------------------------------------------------------------------
__device__ __forceinline__ float fexp(float x) {
    x = fmaxf(x, -87.0f);
    float p = x * 1.44269504088896340f;
    int   ni = __float2int_rn(p);
    float f  = p - (float)ni;
    float t  = f * 0.69314718055994531f;
    float r  = 1.9841269841269841e-4f;
    r = fmaf(r, t, 1.3888888888888889e-3f);
    r = fmaf(r, t, 8.3333333333333333e-3f);
    r = fmaf(r, t, 4.1666666666666664e-2f);
    r = fmaf(r, t, 1.6666666666666666e-1f);
    r = fmaf(r, t, 0.5f);
    r = fmaf(r, t, 1.0f);
    r = fmaf(r, t, 1.0f);
    return r * __int_as_float((ni + 127) << 23);
}

// ---------------------------------------------------------------------------
// score_gemm: E[b,h,q,k] = exp(Q·K^T / 8) in fp16 + per-tile partial row sums.
// One 128x128 tile per block, K=64 single-shot, split-bf16 3-pass HMMA.
// grid (16 ktile, 16 qtile, 32 bh), 256 threads, 2 CTAs/SM.
// ---------------------------------------------------------------------------
#define KSTR 72
#define SA_HI 0
#define SA_LO 18432
#define SB_HI 36864
#define SB_LO 55296
#define RS_O  73728
#define SG_SMEM (73728 + 512)

__global__ __launch_bounds__(256, 2)
void score_gemm(const __nv_bfloat16* __restrict__ QHI, const __nv_bfloat16* __restrict__ QLO,
                const __nv_bfloat16* __restrict__ KHI, const __nv_bfloat16* __restrict__ KLO,
                __half* __restrict__ E, float* __restrict__ rsp)
{
    char* smb = smraw;
    const uint32_t sbase = smem_u32(smb);
    const int tid = threadIdx.x, lane = tid & 31, wid = tid >> 5;
    const int k0 = blockIdx.x * 128, q0 = blockIdx.y * 128;
    const int z = blockIdx.z;                  // b*16 + h
    const int b = z >> 4, h = z & 15;

    const __nv_bfloat16* Qh = QHI + ((size_t)b * Ss + q0) * Dd + h * DKk;
    const __nv_bfloat16* Ql = QLO + ((size_t)b * Ss + q0) * Dd + h * DKk;
    const __nv_bfloat16* Kh = KHI + ((size_t)b * Ss + k0) * Dd + h * DKk;
    const __nv_bfloat16* Kl = KLO + ((size_t)b * Ss + k0) * Dd + h * DKk;

    // load 128x64 tiles (hi+lo for Q and K)
    #pragma unroll
    for (int s = 0; s < 4; ++s) {
        int slot = tid + s * 256;
        int row = slot >> 3, c = (slot & 7) * 8;
        size_t go = (size_t)row * Dd + c;
        uint32_t so = (uint32_t)(row * KSTR + c) * 2;
        cp16(sbase + SA_HI + so, Qh + go);
        cp16(sbase + SA_LO + so, Ql + go);
        cp16(sbase + SB_HI + so, Kh + go);
        cp16(sbase + SB_LO + so, Kl + go);
    }
    CP_COMMIT();
    CP_WAIT(0);
    __syncthreads();

    const int wm = (wid >> 2) * 64;
    const int wn = (wid & 3) * 32;
    uint32_t aoff[4], boff[4];
    #pragma unroll
    for (int mt = 0; mt < 4; ++mt)
        aoff[mt] = ((wm + mt * 16 + (lane & 15)) * KSTR + (lane >> 4) * 8) * 2;
    #pragma unroll
    for (int nt = 0; nt < 4; ++nt)
        boff[nt] = ((wn + nt * 8 + (lane & 7)) * KSTR + ((lane >> 3) & 1) * 8) * 2;

    float d[4][4][4];
    #pragma unroll
    for (int mt = 0; mt < 4; ++mt)
        #pragma unroll
        for (int nt = 0; nt < 4; ++nt)
            #pragma unroll
            for (int i = 0; i < 4; ++i) d[mt][nt][i] = 0.f;

    #pragma unroll
    for (int kk = 0; kk < 4; ++kk) {
        const uint32_t kadd = kk * 32;
        uint32_t ah[4][4], al[4][4], bh[4][2], bl[4][2];
        #pragma unroll
        for (int mt = 0; mt < 4; ++mt) {
            ldsm_x4(ah[mt][0], ah[mt][1], ah[mt][2], ah[mt][3],
                    sbase + SA_HI + aoff[mt] + kadd);
            ldsm_x4(al[mt][0], al[mt][1], al[mt][2], al[mt][3],
                    sbase + SA_LO + aoff[mt] + kadd);
        }
        #pragma unroll
        for (int nt = 0; nt < 4; ++nt) {
            ldsm_x2(bh[nt][0], bh[nt][1], sbase + SB_HI + boff[nt] + kadd);
            ldsm_x2(bl[nt][0], bl[nt][1], sbase + SB_LO + boff[nt] + kadd);
        }
        #pragma unroll
        for (int mt = 0; mt < 4; ++mt)
            #pragma unroll
            for (int nt = 0; nt < 4; ++nt) {
                mma_bf16(d[mt][nt], ah[mt], bh[nt]);
                mma_bf16(d[mt][nt], ah[mt], bl[nt]);
                mma_bf16(d[mt][nt], al[mt], bh[nt]);
            }
    }

    // epilogue: exp, fp16 store, per-tile row sums (deterministic)
    __syncthreads();
    float* rs = (float*)(smb + RS_O);
    if (tid < 128) rs[tid] = 0.f;
    __syncthreads();

    const int g = lane >> 2, c2 = (lane & 3) * 2;
    __half* Eb = E + ((size_t)z * Ss + q0) * Ss + k0;
    #pragma unroll
    for (int mt = 0; mt < 4; ++mt) {
        float r0 = 0.f, r1 = 0.f;
        const int rowA = wm + mt * 16 + g;
        #pragma unroll
        for (int nt = 0; nt < 4; ++nt) {
            int col = wn + nt * 8 + c2;
            float e0 = fexp(d[mt][nt][0] * 0.125f);
            float e1 = fexp(d[mt][nt][1] * 0.125f);
            float e2 = fexp(d[mt][nt][2] * 0.125f);
            float e3 = fexp(d[mt][nt][3] * 0.125f);
            *(__half2*)(Eb + (size_t)rowA * Ss + col)       = __floats2half2_rn(e0, e1);
            *(__half2*)(Eb + (size_t)(rowA + 8) * Ss + col) = __floats2half2_rn(e2, e3);
            r0 += e0 + e1;
            r1 += e2 + e3;
        }
        r0 += __shfl_xor_sync(0xffffffffu, r0, 1);
        r0 += __shfl_xor_sync(0xffffffffu, r0, 2);
        r1 += __shfl_xor_sync(0xffffffffu, r1, 1);
        r1 += __shfl_xor_sync(0xffffffffu, r1, 2);
        if ((lane & 3) == 0) {
            atomicAdd(&rs[rowA], r0);
            atomicAdd(&rs[rowA + 8], r1);
        }
    }
    __syncthreads();
    if (tid < 128)
        rsp[((size_t)z * Ss + q0 + tid) * 16 + blockIdx.x] = rs[tid];
}

// ---------------------------------------------------------------------------
// attn_stream: per (b, 16 q-rows) block; per head: inv from partials, one
// coalesced fp16 pass over E accumulating psum/pmask; rare PV path from E.
// ---------------------------------------------------------------------------
__global__ __launch_bounds__(NT)
void attn_stream(const __half* __restrict__ E, const float* __restrict__ rsp,
                 const float* __restrict__ V, float* __restrict__ merged,
                 float* __restrict__ osum, float* __restrict__ omask)
{
    __shared__ float sm_inv[16];
    const int tid  = threadIdx.x;
    const int lane = tid & 31;
    const int wid  = tid >> 5;
    const int b    = blockIdx.x >> 7;
    const int q0   = (blockIdx.x & 127) * TQ;
    const float* Vb = V + (size_t)b * Ss * Dd;

    float4   psum[TQ];
    uint32_t pm[TQ];
    #pragma unroll
    for (int q = 0; q < TQ; ++q) {
        psum[q] = make_float4(0.f, 0.f, 0.f, 0.f);
        pm[q] = 0u;
    }

    for (int h = 0; h < Hh; ++h) {
        const int z = b * Hh + h;
        const int hd = h * DKk;
        const __half* Eb = E + ((size_t)z * Ss + q0) * Ss;

        __syncthreads();                         // sm_inv reuse guard
        if (tid < 16) {
            const float* rp = rsp + ((size_t)z * Ss + q0 + tid) * 16;
            float s = 0.f;
            #pragma unroll
            for (int i = 0; i < 16; ++i) s += rp[i];
            sm_inv[tid] = 1.0f / s;
        }
        __syncthreads();
        float invf[TQ];
        #pragma unroll
        for (int q = 0; q < TQ; ++q) invf[q] = sm_inv[q];

        uint32_t anyk = 0;
        #pragma unroll
        for (int q = 0; q < TQ; ++q) {
            uint2 uu = *(const uint2*)(Eb + (size_t)q * Ss + tid * 4);
            float2 f01 = __half22float2(*reinterpret_cast<__half2*>(&uu.x));
            float2 f23 = __half22float2(*reinterpret_cast<__half2*>(&uu.y));
            float4 p4;
            p4.x = f01.x * invf[q]; p4.y = f01.y * invf[q];
            p4.z = f23.x * invf[q]; p4.w = f23.y * invf[q];
            uint32_t u = (p4.x >= TH ? 0x1u : 0u) | (p4.y >= TH ? 0x100u : 0u) |
                         (p4.z >= TH ? 0x10000u : 0u) | (p4.w >= TH ? 0x1000000u : 0u);
            pm[q] += u;
            anyk |= u;
            psum[q].x += p4.x; psum[q].y += p4.y;
            psum[q].z += p4.z; psum[q].w += p4.w;
        }
        int any = __syncthreads_or((int)anyk);

        if (any) {
            const float inv = sm_inv[wid];
            const __half* srow = Eb + (size_t)wid * Ss;
            const float* vb2 = Vb + hd + lane * 2;
            float2 ctx = make_float2(0.f, 0.f);
            for (int k = 0; k < Ss; ++k) {
                float p = __half2float(srow[k]) * inv;
                p = (p >= TH) ? p : 0.f;
                float2 vv = *(const float2*)(vb2 + (size_t)k * Dd);
                ctx.x = fmaf(p, vv.x, ctx.x);
                ctx.y = fmaf(p, vv.y, ctx.y);
            }
            *(float2*)(merged + ((size_t)b * Ss + q0 + wid) * Dd + hd + lane * 2) = ctx;
        } else {
            *(float2*)(merged + ((size_t)b * Ss + q0 + wid) * Dd + hd + lane * 2) =
                make_float2(0.f, 0.f);
        }
    }

    #pragma unroll
    for (int q = 0; q < TQ; ++q) {
        size_t row = (size_t)b * Ss + q0 + q;
        ((float4*)(osum + row * Ss))[tid] = psum[q];
        uint32_t u = pm[q];
        float4 f;
        f.x = (float)(u & 255u);
        f.y = (float)((u >> 8) & 255u);
        f.z = (float)((u >> 16) & 255u);
        f.w = (float)(u >> 24);
        ((float4*)(omask + row * Ss))[tid] = f;
    }
}

// ---------------------------------------------------------------------------
extern "C" void kernel_launch(void* const* d_in, const int* in_sizes, int n_in,
                              void* d_out, int out_size)
{
    const float* x  = (const float*)d_in[0];
    const float* Wq = (const float*)d_in[1];
    const float* bq = (const float*)d_in[2];
    const float* Wk = (const float*)d_in[3];
    const float* bk = (const float*)d_in[4];
    const float* Wv = (const float*)d_in[5];
    const float* bv = (const float*)d_in[6];
    const float* Wo = (const float*)d_in[7];
    const float* bo = (const float*)d_in[8];

    float* out   = (float*)d_out;
    float* osum  = out  + (size_t)Bb * Ss * Dd;
    float* omask = osum + (size_t)Bb * Ss * Ss;

    float *q, *k, *v, *m, *rsp;
    __half* e;
    __nv_bfloat16 *qhi, *qlo, *khi, *klo, *xhi, *xlo, *mhi, *mlo, *whi, *wlo;
    cudaGetSymbolAddress((void**)&q,   g_q);
    cudaGetSymbolAddress((void**)&k,   g_k);
    cudaGetSymbolAddress((void**)&v,   g_v);
    cudaGetSymbolAddress((void**)&m,   g_m);
    cudaGetSymbolAddress((void**)&e,   g_e);
    cudaGetSymbolAddress((void**)&rsp, g_rsp);
    cudaGetSymbolAddress((void**)&qhi, g_qhi);
    cudaGetSymbolAddress((void**)&qlo, g_qlo);
    cudaGetSymbolAddress((void**)&khi, g_khi);
    cudaGetSymbolAddress((void**)&klo, g_klo);
    cudaGetSymbolAddress((void**)&xhi, g_xhi);
    cudaGetSymbolAddress((void**)&xlo, g_xlo);
    cudaGetSymbolAddress((void**)&mhi, g_mhi);
    cudaGetSymbolAddress((void**)&mlo, g_mlo);
    cudaGetSymbolAddress((void**)&whi, g_whi);
    cudaGetSymbolAddress((void**)&wlo, g_wlo);

    const int NX = Bb * Ss * Dd;
    const int NW = Dd * Dd;

    split4<<<NX/4/256, 256>>>((const float4*)x, (__nv_bfloat162*)xhi,
                              (__nv_bfloat162*)xlo, NX/4);
    split4w<<<dim3(NW/4/256, 1, 4), 256>>>((const float4*)Wq, (const float4*)Wk,
                                           (const float4*)Wv, (const float4*)Wo,
                                           (__nv_bfloat162*)whi, (__nv_bfloat162*)wlo,
                                           NW/4);

    cudaFuncSetAttribute(gemm_qkv, cudaFuncAttributeMaxDynamicSharedMemorySize, GEMM_SMEM);
    cudaFuncSetAttribute(gemm_o,   cudaFuncAttributeMaxDynamicSharedMemorySize, GEMM_SMEM);
    gemm_qkv<<<dim3(Dd/128, Bb*Ss/128, 3), 256, GEMM_SMEM>>>(
        xhi, xlo, whi, wlo, bq, bk, bv, q, k, v, qhi, qlo, khi, klo, Dd, Dd);

    cudaFuncSetAttribute(score_gemm, cudaFuncAttributeMaxDynamicSharedMemorySize, SG_SMEM);
    score_gemm<<<dim3(Ss/128, Ss/128, Bb*Hh), 256, SG_SMEM>>>(
        qhi, qlo, khi, klo, e, rsp);

    attn_stream<<<Bb * Ss / TQ, NT>>>(e, rsp, v, m, osum, omask);

    split4<<<NX/4/256, 256>>>((const float4*)m, (__nv_bfloat162*)mhi,
                              (__nv_bfloat162*)mlo, NX/4);
    gemm_o<<<dim3(Dd/128, Bb*Ss/128), 256, GEMM_SMEM>>>(
        mhi, mlo, whi + 3*(size_t)NW, wlo + 3*(size_t)NW, bo, out, Dd, Dd);
}